// round 1
// baseline (speedup 1.0000x reference)
#include <cuda_runtime.h>
#include <cuda_bf16.h>
#include <cstdint>

// Problem constants
#define B_ROWS 16384
#define F_FEAT 3
#define C_CARD 256
#define D_EMB  64
#define H_DIM  1024
#define ND_DIM 13
#define K1_PAD 208      // DEEP_IN=205 padded to multiple of 16

// Wide offsets (reference uses cross = cross*F + s, F=3!)
#define OFF_PAIR01  768
#define OFF_PAIR02  (768 + 65536)
#define OFF_PAIR12  (768 + 131072)
#define OFF_TRIPLE  (768 + 196608)
#define OFF_DENSE   16974592

// ---------------- device scratch (no allocs allowed) ----------------
__device__ float g_deepx[(size_t)B_ROWS * K1_PAD];
__device__ float g_w1p[(size_t)H_DIM * K1_PAD];
__device__ float g_wide[B_ROWS];
__device__ float g_h1[(size_t)B_ROWS * H_DIM];
__device__ float g_h2[(size_t)B_ROWS * H_DIM];

// ---------------- helpers ----------------
__device__ __forceinline__ void cp_async16(uint32_t saddr, const void* gptr) {
    asm volatile("cp.async.cg.shared.global [%0], [%1], 16;\n" :: "r"(saddr), "l"(gptr));
}
__device__ __forceinline__ void cp_commit() {
    asm volatile("cp.async.commit_group;\n");
}
__device__ __forceinline__ void cp_wait0() {
    asm volatile("cp.async.wait_group 0;\n");
}

// ---------------- kernel 1: pad W1 into [H, 208] ----------------
__global__ void padw1_kernel(const float* __restrict__ W1) {
    int idx = blockIdx.x * 256 + threadIdx.x;
    if (idx < H_DIM * K1_PAD) {
        int n = idx / K1_PAD;
        int k = idx - n * K1_PAD;
        g_w1p[idx] = (k < F_FEAT * D_EMB + ND_DIM) ? W1[n * (F_FEAT * D_EMB + ND_DIM) + k] : 0.0f;
    }
}

// ---------------- kernel 2: embeddings + wide scalar ----------------
// 256 threads = 4 rows x 64 lanes
__global__ void prep_kernel(const int* __restrict__ sparse,
                            const float* __restrict__ dense,
                            const float* __restrict__ wide_w,
                            const float* __restrict__ wide_b,
                            const float* __restrict__ emb) {
    int local = threadIdx.x >> 6;
    int t = threadIdx.x & 63;
    int row = blockIdx.x * 4 + local;
    if (row >= B_ROWS) return;

    int s0 = sparse[row * 3 + 0];
    int s1 = sparse[row * 3 + 1];
    int s2 = sparse[row * 3 + 2];

    float* dx = g_deepx + (size_t)row * K1_PAD;
    dx[0 * 64 + t] = emb[(0 * 256 + s0) * 64 + t];
    dx[1 * 64 + t] = emb[(1 * 256 + s1) * 64 + t];
    dx[2 * 64 + t] = emb[(2 * 256 + s2) * 64 + t];
    if (t < 16) dx[192 + t] = (t < ND_DIM) ? dense[row * ND_DIM + t] : 0.0f;

    if (t == 0) {
        float w = wide_b[0];
        w += wide_w[s0] + wide_w[256 + s1] + wide_w[512 + s2];
        w += wide_w[OFF_PAIR01 + s0 * 3 + s1];
        w += wide_w[OFF_PAIR02 + s0 * 3 + s2];
        w += wide_w[OFF_PAIR12 + s1 * 3 + s2];
        w += wide_w[OFF_TRIPLE + (s0 * 3 + s1) * 3 + s2];
        const float* dw = wide_w + OFF_DENSE;
        float acc = 0.0f;
        #pragma unroll
        for (int j = 0; j < ND_DIM; j++) acc += dense[row * ND_DIM + j] * dw[j];
        g_wide[row] = w + acc;
    }
}

// ---------------- kernel 3/4: tf32 mma.sync GEMM ----------------
// C[m,n] = relu( sum_k A[m,k] * Bm[n,k] + bias[n] ),  N = 1024
#define BM 128
#define BN 128
#define BK 16
#define SW (BK + 4)   // padded smem row stride (conflict-free frag loads)

__global__ __launch_bounds__(256, 2)
void gemm_tf32_relu(const float* __restrict__ A, int lda,
                    const float* __restrict__ Bm, int ldb,
                    const float* __restrict__ bias,
                    float* __restrict__ C, int K) {
    __shared__ float As[2][BM * SW];
    __shared__ float Bs[2][BN * SW];

    int tid = threadIdx.x;
    int lane = tid & 31;
    int warp = tid >> 5;
    int wm = warp & 3;       // 0..3 -> 32-row strip
    int wn = warp >> 2;      // 0..1 -> 64-col strip
    int bm = blockIdx.y, bn = blockIdx.x;

    const float* Ag = A + (size_t)(bm * BM) * lda;
    const float* Bg = Bm + (size_t)(bn * BN) * ldb;

    float acc[2][8][4];
    #pragma unroll
    for (int i = 0; i < 2; i++)
        #pragma unroll
        for (int j = 0; j < 8; j++)
            #pragma unroll
            for (int q = 0; q < 4; q++) acc[i][j][q] = 0.0f;

    int KT = K / BK;

    // prefetch tile 0
    {
        int k0 = 0;
        #pragma unroll
        for (int i = 0; i < 2; i++) {
            int idx = tid + i * 256;
            int r = idx >> 2, c4 = (idx & 3) * 4;
            cp_async16((uint32_t)__cvta_generic_to_shared(&As[0][r * SW + c4]),
                       Ag + (size_t)r * lda + k0 + c4);
            cp_async16((uint32_t)__cvta_generic_to_shared(&Bs[0][r * SW + c4]),
                       Bg + (size_t)r * ldb + k0 + c4);
        }
        cp_commit();
    }

    for (int kt = 0; kt < KT; kt++) {
        cp_wait0();
        __syncthreads();
        int cur = kt & 1;
        if (kt + 1 < KT) {
            int k0 = (kt + 1) * BK;
            int nxt = cur ^ 1;
            #pragma unroll
            for (int i = 0; i < 2; i++) {
                int idx = tid + i * 256;
                int r = idx >> 2, c4 = (idx & 3) * 4;
                cp_async16((uint32_t)__cvta_generic_to_shared(&As[nxt][r * SW + c4]),
                           Ag + (size_t)r * lda + k0 + c4);
                cp_async16((uint32_t)__cvta_generic_to_shared(&Bs[nxt][r * SW + c4]),
                           Bg + (size_t)r * ldb + k0 + c4);
            }
            cp_commit();
        }

        const float* as = As[cur];
        const float* bs = Bs[cur];
        #pragma unroll
        for (int ks = 0; ks < 2; ks++) {
            int k0 = ks * 8;
            int cA = k0 + (lane & 3);
            uint32_t af[2][4];
            int rbase = wm * 32 + (lane >> 2);
            #pragma unroll
            for (int im = 0; im < 2; im++) {
                int r = rbase + im * 16;
                af[im][0] = __float_as_uint(as[r * SW + cA]);
                af[im][1] = __float_as_uint(as[(r + 8) * SW + cA]);
                af[im][2] = __float_as_uint(as[r * SW + cA + 4]);
                af[im][3] = __float_as_uint(as[(r + 8) * SW + cA + 4]);
            }
            uint32_t bf[8][2];
            int nbase = wn * 64 + (lane >> 2);
            #pragma unroll
            for (int jn = 0; jn < 8; jn++) {
                int n = nbase + jn * 8;
                bf[jn][0] = __float_as_uint(bs[n * SW + cA]);
                bf[jn][1] = __float_as_uint(bs[n * SW + cA + 4]);
            }
            #pragma unroll
            for (int im = 0; im < 2; im++)
                #pragma unroll
                for (int jn = 0; jn < 8; jn++) {
                    asm volatile(
                        "mma.sync.aligned.m16n8k8.row.col.f32.tf32.tf32.f32 "
                        "{%0,%1,%2,%3},{%4,%5,%6,%7},{%8,%9},{%0,%1,%2,%3};\n"
                        : "+f"(acc[im][jn][0]), "+f"(acc[im][jn][1]),
                          "+f"(acc[im][jn][2]), "+f"(acc[im][jn][3])
                        : "r"(af[im][0]), "r"(af[im][1]), "r"(af[im][2]), "r"(af[im][3]),
                          "r"(bf[jn][0]), "r"(bf[jn][1]));
                }
        }
        __syncthreads();
    }

    // epilogue: bias + relu, float2 stores
    #pragma unroll
    for (int im = 0; im < 2; im++) {
        #pragma unroll
        for (int jn = 0; jn < 8; jn++) {
            int m0 = bm * BM + wm * 32 + im * 16 + (lane >> 2);
            int n0 = bn * BN + wn * 64 + jn * 8 + 2 * (lane & 3);
            float bv0 = bias[n0], bv1 = bias[n0 + 1];
            float v0 = acc[im][jn][0] + bv0;
            float v1 = acc[im][jn][1] + bv1;
            float v2 = acc[im][jn][2] + bv0;
            float v3 = acc[im][jn][3] + bv1;
            v0 = fmaxf(v0, 0.0f); v1 = fmaxf(v1, 0.0f);
            v2 = fmaxf(v2, 0.0f); v3 = fmaxf(v3, 0.0f);
            float2* p0 = reinterpret_cast<float2*>(&C[(size_t)m0 * H_DIM + n0]);
            float2* p1 = reinterpret_cast<float2*>(&C[(size_t)(m0 + 8) * H_DIM + n0]);
            *p0 = make_float2(v0, v1);
            *p1 = make_float2(v2, v3);
        }
    }
}

// ---------------- kernel 5: W3 dot + sigmoid ----------------
__global__ void final_kernel(const float* __restrict__ W3,
                             const float* __restrict__ b3,
                             float* __restrict__ out) {
    int warp = threadIdx.x >> 5, lane = threadIdx.x & 31;
    int row = blockIdx.x * 8 + warp;
    if (row >= B_ROWS) return;
    const float* h = g_h2 + (size_t)row * H_DIM;
    float acc = 0.0f;
    #pragma unroll
    for (int k = lane; k < H_DIM; k += 32) acc += h[k] * W3[k];
    #pragma unroll
    for (int o = 16; o; o >>= 1) acc += __shfl_xor_sync(0xffffffffu, acc, o);
    if (lane == 0) {
        float z = g_wide[row] + b3[0] + acc;
        out[row] = 1.0f / (1.0f + expf(-z));
    }
}

// ---------------- launch ----------------
extern "C" void kernel_launch(void* const* d_in, const int* in_sizes, int n_in,
                              void* d_out, int out_size) {
    const int*   sparse = (const int*)d_in[0];
    const float* dense  = (const float*)d_in[1];
    const float* wide_w = (const float*)d_in[2];
    const float* wide_b = (const float*)d_in[3];
    const float* emb    = (const float*)d_in[4];
    const float* W1     = (const float*)d_in[5];
    const float* b1     = (const float*)d_in[6];
    const float* W2     = (const float*)d_in[7];
    const float* b2     = (const float*)d_in[8];
    const float* W3     = (const float*)d_in[9];
    const float* b3     = (const float*)d_in[10];
    float* out = (float*)d_out;

    // 1: pad W1
    padw1_kernel<<<(H_DIM * K1_PAD + 255) / 256, 256>>>(W1);
    // 2: embeddings + wide
    prep_kernel<<<B_ROWS / 4, 256>>>(sparse, dense, wide_w, wide_b, emb);

    float* deepx; cudaGetSymbolAddress((void**)&deepx, g_deepx);
    float* w1p;   cudaGetSymbolAddress((void**)&w1p, g_w1p);
    float* h1;    cudaGetSymbolAddress((void**)&h1, g_h1);
    float* h2;    cudaGetSymbolAddress((void**)&h2, g_h2);

    dim3 grid1(H_DIM / BN, B_ROWS / BM);
    // 3: layer 1 (K=208 padded)
    gemm_tf32_relu<<<grid1, 256>>>(deepx, K1_PAD, w1p, K1_PAD, b1, h1, K1_PAD);
    // 4: layer 2 (K=1024)
    gemm_tf32_relu<<<grid1, 256>>>(h1, H_DIM, W2, H_DIM, b2, h2, H_DIM);
    // 5: final dot + sigmoid
    final_kernel<<<B_ROWS / 8, 256>>>(W3, b3, out);
}

// round 3
// speedup vs baseline: 1.7961x; 1.7961x over previous
#include <cuda_runtime.h>
#include <cuda_bf16.h>
#include <cstdint>

// ---------------- problem constants ----------------
#define B_ROWS 16384
#define H_DIM  1024
#define DEEP_IN 205
#define K1_PAD 208          // multiple of 16
#define ND_DIM 13

// Wide offsets (reference: cross = cross*F + s, F=3)
#define OFF_PAIR01  768
#define OFF_PAIR02  (768 + 65536)
#define OFF_PAIR12  (768 + 131072)
#define OFF_TRIPLE  (768 + 196608)
#define OFF_DENSE   16974592

// ---------------- device scratch ----------------
__device__ float g_deepx[(size_t)B_ROWS * K1_PAD];
__device__ float g_w1p[(size_t)H_DIM * K1_PAD];
__device__ float g_wide[B_ROWS];
__device__ float g_h1[(size_t)B_ROWS * H_DIM];
__device__ float g_part[16 * B_ROWS];

// ---------------- helpers ----------------
__device__ __forceinline__ uint32_t smem_u32(const void* p) {
    uint32_t a;
    asm("{ .reg .u64 t; cvta.to.shared.u64 t, %1; cvt.u32.u64 %0, t; }" : "=r"(a) : "l"(p));
    return a;
}
__device__ __forceinline__ void cp_async16(uint32_t saddr, const void* gptr) {
    asm volatile("cp.async.cg.shared.global [%0], [%1], 16;\n" :: "r"(saddr), "l"(gptr));
}
__device__ __forceinline__ void cp_commit() { asm volatile("cp.async.commit_group;\n"); }

__device__ __forceinline__ void ldsm_x4(uint32_t& r0, uint32_t& r1, uint32_t& r2, uint32_t& r3,
                                        uint32_t addr) {
    asm volatile("ldmatrix.sync.aligned.m8n8.x4.shared.b16 {%0,%1,%2,%3}, [%4];"
                 : "=r"(r0), "=r"(r1), "=r"(r2), "=r"(r3) : "r"(addr));
}

// ---------------- kernel 1: pad W1 into [H, 208] ----------------
__global__ void padw1_kernel(const float* __restrict__ W1) {
    int idx = blockIdx.x * 256 + threadIdx.x;
    if (idx < H_DIM * K1_PAD) {
        int n = idx / K1_PAD;
        int k = idx - n * K1_PAD;
        g_w1p[idx] = (k < DEEP_IN) ? W1[n * DEEP_IN + k] : 0.0f;
    }
}

// ---------------- kernel 2: embeddings + wide scalar ----------------
__global__ void prep_kernel(const int* __restrict__ sparse,
                            const float* __restrict__ dense,
                            const float* __restrict__ wide_w,
                            const float* __restrict__ wide_b,
                            const float* __restrict__ emb) {
    int local = threadIdx.x >> 6;
    int t = threadIdx.x & 63;
    int row = blockIdx.x * 4 + local;

    int s0 = sparse[row * 3 + 0];
    int s1 = sparse[row * 3 + 1];
    int s2 = sparse[row * 3 + 2];

    float* dx = g_deepx + (size_t)row * K1_PAD;
    dx[0 * 64 + t] = emb[(0 * 256 + s0) * 64 + t];
    dx[1 * 64 + t] = emb[(1 * 256 + s1) * 64 + t];
    dx[2 * 64 + t] = emb[(2 * 256 + s2) * 64 + t];
    if (t < 16) dx[192 + t] = (t < ND_DIM) ? dense[row * ND_DIM + t] : 0.0f;

    if (t == 0) {
        float w = wide_b[0];
        w += wide_w[s0] + wide_w[256 + s1] + wide_w[512 + s2];
        w += wide_w[OFF_PAIR01 + s0 * 3 + s1];
        w += wide_w[OFF_PAIR02 + s0 * 3 + s2];
        w += wide_w[OFF_PAIR12 + s1 * 3 + s2];
        w += wide_w[OFF_TRIPLE + (s0 * 3 + s1) * 3 + s2];
        const float* dw = wide_w + OFF_DENSE;
        float acc = 0.0f;
        #pragma unroll
        for (int j = 0; j < ND_DIM; j++) acc += dense[row * ND_DIM + j] * dw[j];
        g_wide[row] = w + acc;
    }
}

// ---------------- tf32 mma.sync GEMM with ldmatrix fragments ----------------
// Tile: BM=128, BN=128, BK=16, 8 warps (warp tile 32x64), 3-stage cp.async.
// Smem rows padded to 80B (5x16B) -> ldmatrix conflict-free.
// mode 0: C = relu(A*B^T + bias)
// mode 1: fused: per-row partial of relu(A*B^T + bias) . W3  -> part[16][B]
#define BK 16
#define ROWB 80                         // bytes per smem row (20 floats)
#define A_BYTES (128 * ROWB)            // 10240
#define STAGE_BYTES (2 * A_BYTES)       // 20480
#define NSTAGE 3
#define SMEM_BYTES (NSTAGE * STAGE_BYTES)  // 61440

__global__ __launch_bounds__(256, 2)
void gemm_tc(const float* __restrict__ A, int lda,
             const float* __restrict__ Bm, int ldb,
             const float* __restrict__ bias,
             float* __restrict__ C,
             const float* __restrict__ W3,
             float* __restrict__ part,
             int KT, int mode) {
    extern __shared__ char smem[];
    uint32_t sb = smem_u32(smem);

    int tid = threadIdx.x;
    int lane = tid & 31;
    int warp = tid >> 5;
    int wm = warp & 3;      // row strip 32
    int wn = warp >> 2;     // col strip 64
    int bn = blockIdx.x, bm = blockIdx.y;

    const float* Ag = A + (size_t)(bm * 128) * lda;
    const float* Bg = Bm + (size_t)(bn * 128) * ldb;

    // ldmatrix per-lane addressing components
    int lrow = lane & 7;
    int lmat = lane >> 3;   // 0..3
    // A: matrices {rows+0,c0},{rows+8,c0},{rows+0,c0+1},{rows+8,c0+1}
    uint32_t aoff0 = (uint32_t)((wm * 32 + ((lmat & 1) << 3) + lrow) * ROWB + ((lmat >> 1) << 4));
    // B: matrices {jn0,c0},{jn0,c0+1},{jn1,c0},{jn1,c0+1}
    uint32_t boff0 = (uint32_t)((wn * 64 + ((lmat >> 1) << 3) + lrow) * ROWB + ((lmat & 1) << 4));

    float acc[2][8][4];
    #pragma unroll
    for (int i = 0; i < 2; i++)
        #pragma unroll
        for (int j = 0; j < 8; j++)
            #pragma unroll
            for (int q = 0; q < 4; q++) acc[i][j][q] = 0.0f;

    auto load_stage = [&](int slot, int k0) {
        uint32_t sA = sb + slot * STAGE_BYTES;
        uint32_t sB = sA + A_BYTES;
        #pragma unroll
        for (int i = 0; i < 4; i++) {
            int idx = i * 256 + tid;
            if (idx < 512) {
                int r = idx >> 2, c = idx & 3;
                cp_async16(sA + r * ROWB + c * 16, Ag + (size_t)r * lda + k0 + c * 4);
            } else {
                int j = idx - 512;
                int r = j >> 2, c = j & 3;
                cp_async16(sB + r * ROWB + c * 16, Bg + (size_t)r * ldb + k0 + c * 4);
            }
        }
        cp_commit();
    };

    load_stage(0, 0);
    load_stage(1, BK);

    for (int kt = 0; kt < KT; kt++) {
        if (kt + 1 < KT) asm volatile("cp.async.wait_group 1;\n" ::: "memory");
        else             asm volatile("cp.async.wait_group 0;\n" ::: "memory");
        __syncthreads();

        if (kt + 2 < KT) load_stage((kt + 2) % NSTAGE, (kt + 2) * BK);

        uint32_t sA = sb + (kt % NSTAGE) * STAGE_BYTES;
        uint32_t sB = sA + A_BYTES;

        #pragma unroll
        for (int ks = 0; ks < 2; ks++) {
            uint32_t af[2][4];
            #pragma unroll
            for (int im = 0; im < 2; im++)
                ldsm_x4(af[im][0], af[im][1], af[im][2], af[im][3],
                        sA + aoff0 + im * (16 * ROWB) + ks * 32);
            uint32_t bf[8][2];
            #pragma unroll
            for (int p = 0; p < 4; p++) {
                uint32_t q0, q1, q2, q3;
                ldsm_x4(q0, q1, q2, q3, sB + boff0 + p * (16 * ROWB) + ks * 32);
                bf[2 * p][0] = q0; bf[2 * p][1] = q1;
                bf[2 * p + 1][0] = q2; bf[2 * p + 1][1] = q3;
            }
            #pragma unroll
            for (int im = 0; im < 2; im++)
                #pragma unroll
                for (int jn = 0; jn < 8; jn++) {
                    asm volatile(
                        "mma.sync.aligned.m16n8k8.row.col.f32.tf32.tf32.f32 "
                        "{%0,%1,%2,%3},{%4,%5,%6,%7},{%8,%9},{%0,%1,%2,%3};\n"
                        : "+f"(acc[im][jn][0]), "+f"(acc[im][jn][1]),
                          "+f"(acc[im][jn][2]), "+f"(acc[im][jn][3])
                        : "r"(af[im][0]), "r"(af[im][1]), "r"(af[im][2]), "r"(af[im][3]),
                          "r"(bf[jn][0]), "r"(bf[jn][1]));
                }
        }
    }

    // ---------------- epilogue ----------------
    int nbase = bn * 128 + wn * 64 + 2 * (lane & 3);
    if (mode == 0) {
        #pragma unroll
        for (int im = 0; im < 2; im++) {
            #pragma unroll
            for (int jn = 0; jn < 8; jn++) {
                int m0 = bm * 128 + wm * 32 + im * 16 + (lane >> 2);
                int n0 = nbase + jn * 8;
                float bv0 = __ldg(bias + n0), bv1 = __ldg(bias + n0 + 1);
                float v0 = fmaxf(acc[im][jn][0] + bv0, 0.0f);
                float v1 = fmaxf(acc[im][jn][1] + bv1, 0.0f);
                float v2 = fmaxf(acc[im][jn][2] + bv0, 0.0f);
                float v3 = fmaxf(acc[im][jn][3] + bv1, 0.0f);
                *reinterpret_cast<float2*>(&C[(size_t)m0 * H_DIM + n0]) = make_float2(v0, v1);
                *reinterpret_cast<float2*>(&C[(size_t)(m0 + 8) * H_DIM + n0]) = make_float2(v2, v3);
            }
        }
    } else {
        // fused relu + W3 dot -> per-row partials (4 rows per thread)
        float pr[4] = {0.0f, 0.0f, 0.0f, 0.0f};
        #pragma unroll
        for (int jn = 0; jn < 8; jn++) {
            int n0 = nbase + jn * 8;
            float bv0 = __ldg(bias + n0), bv1 = __ldg(bias + n0 + 1);
            float w0 = __ldg(W3 + n0), w1 = __ldg(W3 + n0 + 1);
            #pragma unroll
            for (int im = 0; im < 2; im++) {
                float v0 = fmaxf(acc[im][jn][0] + bv0, 0.0f);
                float v1 = fmaxf(acc[im][jn][1] + bv1, 0.0f);
                float v2 = fmaxf(acc[im][jn][2] + bv0, 0.0f);
                float v3 = fmaxf(acc[im][jn][3] + bv1, 0.0f);
                pr[2 * im + 0] += v0 * w0 + v1 * w1;
                pr[2 * im + 1] += v2 * w0 + v3 * w1;
            }
        }
        #pragma unroll
        for (int q = 0; q < 4; q++) {
            pr[q] += __shfl_xor_sync(0xffffffffu, pr[q], 1);
            pr[q] += __shfl_xor_sync(0xffffffffu, pr[q], 2);
        }
        if ((lane & 3) == 0) {
            int slice = bn * 2 + wn;                 // 0..15
            int rbase = bm * 128 + wm * 32 + (lane >> 2);
            float* pp = part + (size_t)slice * B_ROWS + rbase;
            pp[0]  = pr[0];   // rows rbase
            pp[8]  = pr[1];   // rbase+8
            pp[16] = pr[2];   // rbase+16
            pp[24] = pr[3];   // rbase+24
        }
    }
}

// ---------------- final: combine + sigmoid ----------------
__global__ void final_kernel(const float* __restrict__ b3, float* __restrict__ out) {
    int row = blockIdx.x * 256 + threadIdx.x;
    if (row < B_ROWS) {
        float z = g_wide[row] + b3[0];
        #pragma unroll
        for (int s = 0; s < 16; s++) z += g_part[(size_t)s * B_ROWS + row];
        out[row] = 1.0f / (1.0f + expf(-z));
    }
}

// ---------------- launch ----------------
extern "C" void kernel_launch(void* const* d_in, const int* in_sizes, int n_in,
                              void* d_out, int out_size) {
    const int*   sparse = (const int*)d_in[0];
    const float* dense  = (const float*)d_in[1];
    const float* wide_w = (const float*)d_in[2];
    const float* wide_b = (const float*)d_in[3];
    const float* emb    = (const float*)d_in[4];
    const float* W1     = (const float*)d_in[5];
    const float* b1     = (const float*)d_in[6];
    const float* W2     = (const float*)d_in[7];
    const float* b2     = (const float*)d_in[8];
    const float* W3     = (const float*)d_in[9];
    const float* b3     = (const float*)d_in[10];
    float* out = (float*)d_out;

    cudaFuncSetAttribute(gemm_tc, cudaFuncAttributeMaxDynamicSharedMemorySize, SMEM_BYTES);

    padw1_kernel<<<(H_DIM * K1_PAD + 255) / 256, 256>>>(W1);
    prep_kernel<<<B_ROWS / 4, 256>>>(sparse, dense, wide_w, wide_b, emb);

    float* deepx; cudaGetSymbolAddress((void**)&deepx, g_deepx);
    float* w1p;   cudaGetSymbolAddress((void**)&w1p, g_w1p);
    float* h1;    cudaGetSymbolAddress((void**)&h1, g_h1);
    float* partp; cudaGetSymbolAddress((void**)&partp, g_part);

    dim3 grid(H_DIM / 128, B_ROWS / 128);   // (8, 128)
    // layer 1: K=208, store relu to h1
    gemm_tc<<<grid, 256, SMEM_BYTES>>>(deepx, K1_PAD, w1p, K1_PAD, b1, h1,
                                       nullptr, nullptr, K1_PAD / BK, 0);
    // layer 2: K=1024, fused relu + W3 dot -> partials
    gemm_tc<<<grid, 256, SMEM_BYTES>>>(h1, H_DIM, W2, H_DIM, b2, nullptr,
                                       W3, partp, H_DIM / BK, 1);
    final_kernel<<<(B_ROWS + 255) / 256, 256>>>(b3, out);
}

// round 4
// speedup vs baseline: 3.2241x; 1.7951x over previous
#include <cuda_runtime.h>
#include <cuda_fp16.h>
#include <cstdint>

// ---------------- problem constants ----------------
#define B_ROWS 16384
#define H_DIM  1024
#define DEEP_IN 205
#define K1_PAD 224          // multiple of 32
#define ND_DIM 13

// Wide offsets (reference: cross = cross*F + s, F=3)
#define OFF_PAIR01  768
#define OFF_PAIR02  (768 + 65536)
#define OFF_PAIR12  (768 + 131072)
#define OFF_TRIPLE  (768 + 196608)
#define OFF_DENSE   16974592

// ---------------- device scratch ----------------
__device__ __half g_deepx[(size_t)B_ROWS * K1_PAD];
__device__ __half g_w1h[(size_t)H_DIM * K1_PAD];
__device__ __half g_w2h[(size_t)H_DIM * H_DIM];
__device__ float  g_wide[B_ROWS];
__device__ __half g_h1[(size_t)B_ROWS * H_DIM];
__device__ float  g_part[16 * B_ROWS];

// ---------------- helpers ----------------
__device__ __forceinline__ uint32_t smem_u32(const void* p) {
    uint32_t a;
    asm("{ .reg .u64 t; cvta.to.shared.u64 t, %1; cvt.u32.u64 %0, t; }" : "=r"(a) : "l"(p));
    return a;
}
__device__ __forceinline__ void cp_async16(uint32_t saddr, const void* gptr) {
    asm volatile("cp.async.cg.shared.global [%0], [%1], 16;\n" :: "r"(saddr), "l"(gptr));
}
__device__ __forceinline__ void cp_commit() { asm volatile("cp.async.commit_group;\n"); }

__device__ __forceinline__ void ldsm_x4(uint32_t& r0, uint32_t& r1, uint32_t& r2, uint32_t& r3,
                                        uint32_t addr) {
    asm volatile("ldmatrix.sync.aligned.m8n8.x4.shared.b16 {%0,%1,%2,%3}, [%4];"
                 : "=r"(r0), "=r"(r1), "=r"(r2), "=r"(r3) : "r"(addr));
}

// ---------------- kernel 1: pad+convert W1 -> [H, 224] fp16 ----------------
__global__ void padw1_kernel(const float* __restrict__ W1) {
    int idx = blockIdx.x * 256 + threadIdx.x;
    if (idx < H_DIM * K1_PAD) {
        int n = idx / K1_PAD;
        int k = idx - n * K1_PAD;
        g_w1h[idx] = __float2half((k < DEEP_IN) ? W1[n * DEEP_IN + k] : 0.0f);
    }
}

// ---------------- kernel 1b: convert W2 -> fp16 ----------------
__global__ void convw2_kernel(const float* __restrict__ W2) {
    int idx = blockIdx.x * 256 + threadIdx.x;
    float2 v = *reinterpret_cast<const float2*>(W2 + idx * 2);
    __half2 h = __floats2half2_rn(v.x, v.y);
    *reinterpret_cast<__half2*>(g_w2h + idx * 2) = h;
}

// ---------------- kernel 2: embeddings (fp16) + wide scalar ----------------
__global__ void prep_kernel(const int* __restrict__ sparse,
                            const float* __restrict__ dense,
                            const float* __restrict__ wide_w,
                            const float* __restrict__ wide_b,
                            const float* __restrict__ emb) {
    int local = threadIdx.x >> 6;
    int t = threadIdx.x & 63;
    int row = blockIdx.x * 4 + local;

    int s0 = sparse[row * 3 + 0];
    int s1 = sparse[row * 3 + 1];
    int s2 = sparse[row * 3 + 2];

    __half* dx = g_deepx + (size_t)row * K1_PAD;
    dx[0 * 64 + t] = __float2half(emb[(0 * 256 + s0) * 64 + t]);
    dx[1 * 64 + t] = __float2half(emb[(1 * 256 + s1) * 64 + t]);
    dx[2 * 64 + t] = __float2half(emb[(2 * 256 + s2) * 64 + t]);
    if (t < 32) dx[192 + t] = __float2half((t < ND_DIM) ? dense[row * ND_DIM + t] : 0.0f);

    if (t == 0) {
        float w = wide_b[0];
        w += wide_w[s0] + wide_w[256 + s1] + wide_w[512 + s2];
        w += wide_w[OFF_PAIR01 + s0 * 3 + s1];
        w += wide_w[OFF_PAIR02 + s0 * 3 + s2];
        w += wide_w[OFF_PAIR12 + s1 * 3 + s2];
        w += wide_w[OFF_TRIPLE + (s0 * 3 + s1) * 3 + s2];
        const float* dw = wide_w + OFF_DENSE;
        float acc = 0.0f;
        #pragma unroll
        for (int j = 0; j < ND_DIM; j++) acc += dense[row * ND_DIM + j] * dw[j];
        g_wide[row] = w + acc;
    }
}

// ---------------- fp16 mma.sync GEMM (f32 accum) ----------------
// Tile: BM=128, BN=128, BK=32, 8 warps (warp tile 32x64), 4-stage cp.async.
// Smem rows: 32 halfs = 64B data + 16B pad = 80B -> ldmatrix conflict-free.
// mode 0: C(half) = relu(A*B^T + bias)
// mode 1: fused: per-row partial of relu(A*B^T + bias) . W3 -> part[16][B]
#define BK 32
#define ROWB 80
#define A_BYTES (128 * ROWB)            // 10240
#define STAGE_BYTES (2 * A_BYTES)       // 20480
#define NSTAGE 4
#define SMEM_BYTES (NSTAGE * STAGE_BYTES)  // 81920

__global__ __launch_bounds__(256, 2)
void gemm_tc(const __half* __restrict__ A, int lda,
             const __half* __restrict__ Bm, int ldb,
             const float* __restrict__ bias,
             __half* __restrict__ C,
             const float* __restrict__ W3,
             float* __restrict__ part,
             int KT, int mode) {
    extern __shared__ char smem[];
    uint32_t sb = smem_u32(smem);

    int tid = threadIdx.x;
    int lane = tid & 31;
    int warp = tid >> 5;
    int wm = warp & 3;      // 32-row strip
    int wn = warp >> 2;     // 64-col strip
    int bn = blockIdx.x, bm = blockIdx.y;

    const __half* Ag = A + (size_t)(bm * 128) * lda;
    const __half* Bg = Bm + (size_t)(bn * 128) * ldb;

    int lrow = lane & 7;
    int lmat = lane >> 3;
    // A x4: (m,k0),(m+8,k0),(m,k8),(m+8,k8)
    uint32_t aoff0 = (uint32_t)((wm * 32 + ((lmat & 1) << 3) + lrow) * ROWB + ((lmat >> 1) << 4));
    // B x4: (n,k0),(n,k8),(n+8,k0),(n+8,k8)
    uint32_t boff0 = (uint32_t)((wn * 64 + ((lmat >> 1) << 3) + lrow) * ROWB + ((lmat & 1) << 4));

    float acc[2][8][4];
    #pragma unroll
    for (int i = 0; i < 2; i++)
        #pragma unroll
        for (int j = 0; j < 8; j++)
            #pragma unroll
            for (int q = 0; q < 4; q++) acc[i][j][q] = 0.0f;

    auto load_stage = [&](int slot, int k0) {
        uint32_t sA = sb + slot * STAGE_BYTES;
        uint32_t sB = sA + A_BYTES;
        #pragma unroll
        for (int i = 0; i < 4; i++) {
            int idx = i * 256 + tid;
            if (idx < 512) {
                int r = idx >> 2, c = idx & 3;
                cp_async16(sA + r * ROWB + c * 16, Ag + (size_t)r * lda + k0 + c * 8);
            } else {
                int j = idx - 512;
                int r = j >> 2, c = j & 3;
                cp_async16(sB + r * ROWB + c * 16, Bg + (size_t)r * ldb + k0 + c * 8);
            }
        }
        cp_commit();
    };

    // prologue: 3 stages in flight
    load_stage(0, 0);
    load_stage(1, BK);
    if (KT > 2) load_stage(2, 2 * BK); else cp_commit();

    for (int kt = 0; kt < KT; kt++) {
        asm volatile("cp.async.wait_group 2;\n" ::: "memory");
        __syncthreads();

        if (kt + 3 < KT) load_stage((kt + 3) % NSTAGE, (kt + 3) * BK);
        else cp_commit();   // keep group accounting uniform

        uint32_t sA = sb + (kt % NSTAGE) * STAGE_BYTES;
        uint32_t sB = sA + A_BYTES;

        #pragma unroll
        for (int ks = 0; ks < 2; ks++) {     // two k16 steps within BK=32
            uint32_t af[2][4];
            #pragma unroll
            for (int im = 0; im < 2; im++)
                ldsm_x4(af[im][0], af[im][1], af[im][2], af[im][3],
                        sA + aoff0 + im * (16 * ROWB) + ks * 32);
            uint32_t bf[8][2];
            #pragma unroll
            for (int p = 0; p < 4; p++) {
                uint32_t q0, q1, q2, q3;
                ldsm_x4(q0, q1, q2, q3, sB + boff0 + p * (16 * ROWB) + ks * 32);
                bf[2 * p][0] = q0; bf[2 * p][1] = q1;
                bf[2 * p + 1][0] = q2; bf[2 * p + 1][1] = q3;
            }
            #pragma unroll
            for (int im = 0; im < 2; im++)
                #pragma unroll
                for (int jn = 0; jn < 8; jn++) {
                    asm volatile(
                        "mma.sync.aligned.m16n8k16.row.col.f32.f16.f16.f32 "
                        "{%0,%1,%2,%3},{%4,%5,%6,%7},{%8,%9},{%0,%1,%2,%3};\n"
                        : "+f"(acc[im][jn][0]), "+f"(acc[im][jn][1]),
                          "+f"(acc[im][jn][2]), "+f"(acc[im][jn][3])
                        : "r"(af[im][0]), "r"(af[im][1]), "r"(af[im][2]), "r"(af[im][3]),
                          "r"(bf[jn][0]), "r"(bf[jn][1]));
                }
        }
        __syncthreads();
    }

    // ---------------- epilogue ----------------
    int nbase = bn * 128 + wn * 64 + 2 * (lane & 3);
    if (mode == 0) {
        #pragma unroll
        for (int im = 0; im < 2; im++) {
            #pragma unroll
            for (int jn = 0; jn < 8; jn++) {
                int m0 = bm * 128 + wm * 32 + im * 16 + (lane >> 2);
                int n0 = nbase + jn * 8;
                float bv0 = __ldg(bias + n0), bv1 = __ldg(bias + n0 + 1);
                float v0 = fmaxf(acc[im][jn][0] + bv0, 0.0f);
                float v1 = fmaxf(acc[im][jn][1] + bv1, 0.0f);
                float v2 = fmaxf(acc[im][jn][2] + bv0, 0.0f);
                float v3 = fmaxf(acc[im][jn][3] + bv1, 0.0f);
                *reinterpret_cast<__half2*>(&C[(size_t)m0 * H_DIM + n0]) = __floats2half2_rn(v0, v1);
                *reinterpret_cast<__half2*>(&C[(size_t)(m0 + 8) * H_DIM + n0]) = __floats2half2_rn(v2, v3);
            }
        }
    } else {
        float pr[4] = {0.0f, 0.0f, 0.0f, 0.0f};
        #pragma unroll
        for (int jn = 0; jn < 8; jn++) {
            int n0 = nbase + jn * 8;
            float bv0 = __ldg(bias + n0), bv1 = __ldg(bias + n0 + 1);
            float w0 = __ldg(W3 + n0), w1 = __ldg(W3 + n0 + 1);
            #pragma unroll
            for (int im = 0; im < 2; im++) {
                float v0 = fmaxf(acc[im][jn][0] + bv0, 0.0f);
                float v1 = fmaxf(acc[im][jn][1] + bv1, 0.0f);
                float v2 = fmaxf(acc[im][jn][2] + bv0, 0.0f);
                float v3 = fmaxf(acc[im][jn][3] + bv1, 0.0f);
                pr[2 * im + 0] += v0 * w0 + v1 * w1;
                pr[2 * im + 1] += v2 * w0 + v3 * w1;
            }
        }
        #pragma unroll
        for (int q = 0; q < 4; q++) {
            pr[q] += __shfl_xor_sync(0xffffffffu, pr[q], 1);
            pr[q] += __shfl_xor_sync(0xffffffffu, pr[q], 2);
        }
        if ((lane & 3) == 0) {
            int slice = bn * 2 + wn;
            int rbase = bm * 128 + wm * 32 + (lane >> 2);
            float* pp = part + (size_t)slice * B_ROWS + rbase;
            pp[0]  = pr[0];
            pp[8]  = pr[1];
            pp[16] = pr[2];
            pp[24] = pr[3];
        }
    }
}

// ---------------- final: combine + sigmoid ----------------
__global__ void final_kernel(const float* __restrict__ b3, float* __restrict__ out) {
    int row = blockIdx.x * 256 + threadIdx.x;
    if (row < B_ROWS) {
        float z = g_wide[row] + b3[0];
        #pragma unroll
        for (int s = 0; s < 16; s++) z += g_part[(size_t)s * B_ROWS + row];
        out[row] = 1.0f / (1.0f + expf(-z));
    }
}

// ---------------- launch ----------------
extern "C" void kernel_launch(void* const* d_in, const int* in_sizes, int n_in,
                              void* d_out, int out_size) {
    const int*   sparse = (const int*)d_in[0];
    const float* dense  = (const float*)d_in[1];
    const float* wide_w = (const float*)d_in[2];
    const float* wide_b = (const float*)d_in[3];
    const float* emb    = (const float*)d_in[4];
    const float* W1     = (const float*)d_in[5];
    const float* b1     = (const float*)d_in[6];
    const float* W2     = (const float*)d_in[7];
    const float* b2     = (const float*)d_in[8];
    const float* W3     = (const float*)d_in[9];
    const float* b3     = (const float*)d_in[10];
    float* out = (float*)d_out;

    cudaFuncSetAttribute(gemm_tc, cudaFuncAttributeMaxDynamicSharedMemorySize, SMEM_BYTES);

    padw1_kernel<<<(H_DIM * K1_PAD + 255) / 256, 256>>>(W1);
    convw2_kernel<<<(H_DIM * H_DIM / 2) / 256, 256>>>(W2);
    prep_kernel<<<B_ROWS / 4, 256>>>(sparse, dense, wide_w, wide_b, emb);

    __half* deepx; cudaGetSymbolAddress((void**)&deepx, g_deepx);
    __half* w1h;   cudaGetSymbolAddress((void**)&w1h, g_w1h);
    __half* w2h;   cudaGetSymbolAddress((void**)&w2h, g_w2h);
    __half* h1;    cudaGetSymbolAddress((void**)&h1, g_h1);
    float* partp;  cudaGetSymbolAddress((void**)&partp, g_part);

    dim3 grid(H_DIM / 128, B_ROWS / 128);   // (8, 128)
    // layer 1: K=224, store relu(h1) as fp16
    gemm_tc<<<grid, 256, SMEM_BYTES>>>(deepx, K1_PAD, w1h, K1_PAD, b1, h1,
                                       nullptr, nullptr, K1_PAD / BK, 0);
    // layer 2: K=1024, fused relu + W3 dot -> partials
    gemm_tc<<<grid, 256, SMEM_BYTES>>>(h1, H_DIM, w2h, H_DIM, b2, nullptr,
                                       W3, partp, H_DIM / BK, 1);
    final_kernel<<<(B_ROWS + 255) / 256, 256>>>(b3, out);
}